// round 7
// baseline (speedup 1.0000x reference)
#include <cuda_runtime.h>
#include <cuda_bf16.h>

#define EPSF 1e-5f

// Problem dims
#define NN  64
#define CC  64
#define TD  300
#define VV  25
#define SS  3
#define ICn 16
#define OCn 64

// kConv tiling
#define TCB   20
#define NTCB  (TD/TCB)        // 15
#define COLSB (TCB*VV)        // 500

// kM tiling
#define NCH  5
#define KTOT (ICn*TD)         // 4800
#define KCH  (KTOT/NCH)       // 960
#define KST  64
#define NSTG (KCH/KST)        // 15

// kB tiling
#define TTB4  4
#define COLS4 (TTB4*VV)       // 100 cols per block
#define NTB4  (TD/TTB4)       // 75
#define ZST   68              // z row stride (16B aligned, 4-way STS conflict accepted)

typedef unsigned long long u64;

__device__ __nv_bfloat162 g_ab[(size_t)NN*SS*KTOT*32];
__device__ float g_Mpart[NCH*NN*SS*VV*VV];
__device__ float g_Aadp [NN*SS*VV*VV];
__device__ float g_wdT  [SS*CC*OCn];   // [s][c][o], BN scale folded
__device__ float g_off  [OCn];

__device__ __forceinline__ float tanh_fast(float x) {
    float y;
    asm("tanh.approx.f32 %0, %1;" : "=f"(y) : "f"(x));
    return y;
}
__device__ __forceinline__ u64 pack2(float lo, float hi) {
    u64 r; asm("mov.b64 %0, {%1, %2};" : "=l"(r) : "f"(lo), "f"(hi)); return r;
}
__device__ __forceinline__ float2 unpack2(u64 p) {
    float2 r; asm("mov.b64 {%0, %1}, %2;" : "=f"(r.x), "=f"(r.y) : "l"(p)); return r;
}
__device__ __forceinline__ void fma2(u64& d, u64 a, u64 b) {
    asm("fma.rn.f32x2 %0, %1, %2, %0;" : "+l"(d) : "l"(a), "l"(b));
}

// ---------------------------------------------------------------------------
// kConv: a = tanh(bn(Wa x)), b = tanh(bn(Wb x)) -> g_ab (bf16 pairs).
// ---------------------------------------------------------------------------
__global__ __launch_bounds__(256) void kConv(
    const float* __restrict__ x,
    const float* __restrict__ wa, const float* __restrict__ ba,
    const float* __restrict__ wb, const float* __restrict__ bb,
    const float* __restrict__ gag, const float* __restrict__ gab,
    const float* __restrict__ gam, const float* __restrict__ gav,
    const float* __restrict__ gbg, const float* __restrict__ gbb,
    const float* __restrict__ gbm, const float* __restrict__ gbv)
{
    __shared__ __align__(16) float s_w[CC*32];
    __shared__ float s_sha[ICn], s_shb[ICn];

    const int tid = threadIdx.x;
    const int tc  = blockIdx.x;
    const int s   = blockIdx.y;
    const int n   = blockIdx.z;

    for (int idx = tid; idx < ICn*CC; idx += 256) {
        int i = idx / CC, c = idx % CC;
        float sca = gag[s*ICn+i] * rsqrtf(gav[s*ICn+i] + EPSF);
        float scb = gbg[s*ICn+i] * rsqrtf(gbv[s*ICn+i] + EPSF);
        s_w[c*32 + i]      = wa[s*ICn*CC + idx] * sca;
        s_w[c*32 + 16 + i] = wb[s*ICn*CC + idx] * scb;
    }
    if (tid < ICn) {
        float sca = gag[s*ICn+tid] * rsqrtf(gav[s*ICn+tid] + EPSF);
        float scb = gbg[s*ICn+tid] * rsqrtf(gbv[s*ICn+tid] + EPSF);
        s_sha[tid] = (ba[s*ICn+tid] - gam[s*ICn+tid]) * sca + gab[s*ICn+tid];
        s_shb[tid] = (bb[s*ICn+tid] - gbm[s*ICn+tid]) * scb + gbb[s*ICn+tid];
    }
    __syncthreads();
    if (tid >= COLSB/2) return;

    const int col0 = tc*COLSB + 2*tid;
    const int col1 = col0 + 1;
    const int t0 = col0 / 25, v0 = col0 - 25*t0;
    const int t1 = col1 / 25, v1 = col1 - 25*t1;

    u64 accA0[8], accA1[8], accB0[8], accB1[8];
    #pragma unroll
    for (int p = 0; p < 8; p++) {
        u64 ia = pack2(s_sha[2*p], s_sha[2*p+1]);
        u64 ib = pack2(s_shb[2*p], s_shb[2*p+1]);
        accA0[p] = ia; accA1[p] = ia;
        accB0[p] = ib; accB1[p] = ib;
    }

    const float* xp = x + (size_t)n*(CC*TD*VV) + col0;
    #pragma unroll 4
    for (int c = 0; c < CC; c++) {
        float2 xv = *reinterpret_cast<const float2*>(xp + (size_t)c*(TD*VV));
        u64 xd0 = pack2(xv.x, xv.x);
        u64 xd1 = pack2(xv.y, xv.y);
        const ulonglong2* wrow = reinterpret_cast<const ulonglong2*>(&s_w[c*32]);
        #pragma unroll
        for (int g = 0; g < 4; g++) {
            ulonglong2 w2 = wrow[g];
            fma2(accA0[2*g],   w2.x, xd0); fma2(accA1[2*g],   w2.x, xd1);
            fma2(accA0[2*g+1], w2.y, xd0); fma2(accA1[2*g+1], w2.y, xd1);
        }
        #pragma unroll
        for (int g = 0; g < 4; g++) {
            ulonglong2 w2 = wrow[4+g];
            fma2(accB0[2*g],   w2.x, xd0); fma2(accB1[2*g],   w2.x, xd1);
            fma2(accB0[2*g+1], w2.y, xd0); fma2(accB1[2*g+1], w2.y, xd1);
        }
    }

    __nv_bfloat162* gb = g_ab + (size_t)(n*SS + s)*KTOT*32;
    #pragma unroll
    for (int p = 0; p < 8; p++) {
        float2 a0 = unpack2(accA0[p]);
        float2 b0 = unpack2(accB0[p]);
        float2 a1 = unpack2(accA1[p]);
        float2 b1 = unpack2(accB1[p]);
        __nv_bfloat162 h;
        h.x = __float2bfloat16(tanh_fast(a0.x));
        h.y = __float2bfloat16(tanh_fast(b0.x));
        gb[(size_t)(t0*ICn + 2*p)*32 + v0] = h;
        h.x = __float2bfloat16(tanh_fast(a0.y));
        h.y = __float2bfloat16(tanh_fast(b0.y));
        gb[(size_t)(t0*ICn + 2*p+1)*32 + v0] = h;
        h.x = __float2bfloat16(tanh_fast(a1.x));
        h.y = __float2bfloat16(tanh_fast(b1.x));
        gb[(size_t)(t1*ICn + 2*p)*32 + v1] = h;
        h.x = __float2bfloat16(tanh_fast(a1.y));
        h.y = __float2bfloat16(tanh_fast(b1.y));
        gb[(size_t)(t1*ICn + 2*p+1)*32 + v1] = h;
    }
}

// ---------------------------------------------------------------------------
// kM: partial M over 960 rows.
// ---------------------------------------------------------------------------
__global__ __launch_bounds__(256) void kM()
{
    __shared__ __align__(16) float s_a32[KST*32];
    __shared__ __align__(16) float s_b32[KST*32];

    const int tid  = threadIdx.x;
    const int wid  = tid >> 5;
    const int lane = tid & 31;
    const int chunk = blockIdx.x;
    const int s     = blockIdx.y;
    const int n     = blockIdx.z;

    const uint4* gsrc = reinterpret_cast<const uint4*>(
        g_ab + ((size_t)(n*SS + s)*KTOT + (size_t)chunk*KCH)*32);

    u64 macc[2] = {0ull, 0ull};

    for (int st = 0; st < NSTG; st++) {
        __syncthreads();
        #pragma unroll
        for (int rep = 0; rep < 2; rep++) {
            int u = tid + rep*256;
            uint4 val = gsrc[st*512 + u];
            int row = u >> 3, q = u & 7;
            float* pa = &s_a32[row*32 + q*4];
            float* pb = &s_b32[row*32 + q*4];
            float2 f0 = __bfloat1622float2(*reinterpret_cast<__nv_bfloat162*>(&val.x));
            float2 f1 = __bfloat1622float2(*reinterpret_cast<__nv_bfloat162*>(&val.y));
            float2 f2 = __bfloat1622float2(*reinterpret_cast<__nv_bfloat162*>(&val.z));
            float2 f3 = __bfloat1622float2(*reinterpret_cast<__nv_bfloat162*>(&val.w));
            pa[0] = f0.x; pb[0] = f0.y;
            pa[1] = f1.x; pb[1] = f1.y;
            pa[2] = f2.x; pb[2] = f2.y;
            pa[3] = f3.x; pb[3] = f3.y;
        }
        __syncthreads();
        #pragma unroll 8
        for (int kk = 0; kk < KST; kk++) {
            float av = s_a32[kk*32 + lane];
            u64 ap = pack2(av, av);
            ulonglong2 bv = *reinterpret_cast<const ulonglong2*>(
                &s_b32[kk*32 + wid*4]);
            fma2(macc[0], ap, bv.x);
            fma2(macc[1], ap, bv.y);
        }
    }

    if (lane < VV) {
        float* mp = &g_Mpart[((size_t)chunk*NN*SS + (size_t)n*SS + s)*(VV*VV)];
        float2 m0 = unpack2(macc[0]);
        float2 m1 = unpack2(macc[1]);
        int w = wid*4;
        if (w   < VV) mp[lane*VV + w]   = m0.x;
        if (w+1 < VV) mp[lane*VV + w+1] = m0.y;
        if (w+2 < VV) mp[lane*VV + w+2] = m1.x;
        if (w+3 < VV) mp[lane*VV + w+3] = m1.y;
    }
}

// ---------------------------------------------------------------------------
// kA2: reduce partials, A_adp = A + tanh(M/(IC*T)) * alpha
// ---------------------------------------------------------------------------
__global__ void kA2(const float* __restrict__ A, const float* __restrict__ alpha)
{
    int idx = blockIdx.x * 256 + threadIdx.x;
    if (idx >= NN*SS*VV*VV) return;
    float m = 0.f;
    #pragma unroll
    for (int ch = 0; ch < NCH; ch++)
        m += g_Mpart[ch*(NN*SS*VV*VV) + idx];
    g_Aadp[idx] = A[idx % (SS*VV*VV)]
                + tanhf(m * (1.f/(float)(ICn*TD))) * alpha[0];
}

// ---------------------------------------------------------------------------
// kW: transpose conv_d weights to [s][c][o] with BN scale folded; g_off.
// ---------------------------------------------------------------------------
__global__ void kW(const float* __restrict__ wd, const float* __restrict__ db,
                   const float* __restrict__ bng, const float* __restrict__ bnb,
                   const float* __restrict__ bnm, const float* __restrict__ bnv)
{
    int idx = blockIdx.x * 256 + threadIdx.x;
    if (idx < SS*OCn*CC) {
        int c = idx & 63;
        int o = (idx >> 6) & 63;
        int s = idx >> 12;
        float sc = bng[o] * rsqrtf(bnv[o] + EPSF);
        g_wdT[s*(CC*OCn) + c*OCn + o] = wd[idx] * sc;
    }
    if (blockIdx.x == 0 && threadIdx.x < OCn) {
        int o = threadIdx.x;
        float sc = bng[o] * rsqrtf(bnv[o] + EPSF);
        float ds = db[o] + db[OCn + o] + db[2*OCn + o];
        g_off[o] = (ds - bnm[o]) * sc + bnb[o];
    }
}

// ---------------------------------------------------------------------------
// kB: per (t-tile of 4, n): for each s:
//   stage Z: z[o][col] = WdT_s @ x_tile   (K=64; Wd bcast, x lane-consecutive)
//   stage Y: y[o][col] += z @ A_adp_s     (K=25; z bcast, A lane-consecutive)
// Epilogue: y + off + x residual, ReLU.  All smem accesses conflict-free
// except the z STS (4-way, accepted).
// ---------------------------------------------------------------------------
__global__ __launch_bounds__(256, 2) void kB(
    const float* __restrict__ x,
    float* __restrict__ out)
{
    extern __shared__ float sm[];
    float* s_x   = sm;                     // [c][100]        6400 f
    float* s_z   = s_x + CC*COLS4;         // [col][ZST=68]   6800 f
    float* s_wd  = s_z + COLS4*ZST;        // [c][64]         4096 f
    float* s_A   = s_wd + CC*OCn;          // [s][v][32]      2400 f
    float* s_off = s_A + SS*VV*32;         // 64 f

    const int tid  = threadIdx.x;
    const int wid  = tid >> 5;
    const int lane = tid & 31;
    const int tb = blockIdx.x;
    const int n  = blockIdx.y;
    const int c0 = tb * COLS4;

    // ---- prologue staging ----
    // x tile [c][100], float4 coalesced (7500 and 100 are mult of 4)
    {
        const float4* xg = reinterpret_cast<const float4*>(
            x + (size_t)n*(CC*TD*VV));
        for (int idx = tid; idx < CC*(COLS4/4); idx += 256) {
            int c = idx / (COLS4/4), j = idx % (COLS4/4);
            float4 v = xg[(c*(TD*VV) + c0)/4 + j];
            *reinterpret_cast<float4*>(&s_x[c*COLS4 + j*4]) = v;
        }
    }
    // A_adp padded [s][v][32], zero for w>=25
    for (int idx = tid; idx < SS*VV*32; idx += 256) {
        int s = idx / (VV*32);
        int r = idx - s*(VV*32);
        int v = r >> 5, w = r & 31;
        s_A[idx] = (w < VV)
                 ? g_Aadp[((size_t)n*SS + s)*(VV*VV) + v*VV + w] : 0.f;
    }
    if (tid < OCn) s_off[tid] = g_off[tid];

    // stage-Z mapping: warp = (oq = wid&3, colhalf = wid>>2)
    const int oqz    = (wid & 3) * 16;          // 16 o's
    const int colz0  = (wid >> 2) * 50 + lane;  // col A (lane<25)
    const int colz1  = colz0 + 25;              // col B
    const bool zact  = (lane < VV);
    // stage-Y mapping: warp = (lt = wid&3, ohalf = wid>>2)
    const int lt     = wid & 3;
    const int oby    = (wid >> 2) * 32;         // 32 o's

    u64 yac[16];
    #pragma unroll
    for (int j = 0; j < 16; j++) yac[j] = 0ull;

    for (int s = 0; s < SS; s++) {
        __syncthreads();   // prior stage-Y done; s_wd/s_z reusable
        {
            const float4* wg = reinterpret_cast<const float4*>(
                g_wdT + s*(CC*OCn));
            float4* ws = reinterpret_cast<float4*>(s_wd);
            for (int idx = tid; idx < CC*OCn/4; idx += 256)
                ws[idx] = wg[idx];
        }
        __syncthreads();

        // ---- stage Z: z[o][col] = sum_c wdT[c][o] * x[c][col] ----
        u64 zacA[8], zacB[8];
        #pragma unroll
        for (int j = 0; j < 8; j++) { zacA[j] = 0ull; zacB[j] = 0ull; }
        {
            const float* xpA = &s_x[colz0];
            const float* xpB = &s_x[colz1];
            #pragma unroll 8
            for (int c = 0; c < CC; c++) {
                float xa = xpA[c*COLS4];
                float xb = xpB[c*COLS4];
                u64 xdA = pack2(xa, xa);
                u64 xdB = pack2(xb, xb);
                const ulonglong2* wq = reinterpret_cast<const ulonglong2*>(
                    &s_wd[c*OCn + oqz]);
                #pragma unroll
                for (int k = 0; k < 4; k++) {
                    ulonglong2 w2 = wq[k];
                    fma2(zacA[2*k],   w2.x, xdA);
                    fma2(zacA[2*k+1], w2.y, xdA);
                    fma2(zacB[2*k],   w2.x, xdB);
                    fma2(zacB[2*k+1], w2.y, xdB);
                }
            }
        }
        if (zact) {
            ulonglong2* zrA = reinterpret_cast<ulonglong2*>(
                &s_z[colz0*ZST + oqz]);
            ulonglong2* zrB = reinterpret_cast<ulonglong2*>(
                &s_z[colz1*ZST + oqz]);
            #pragma unroll
            for (int k = 0; k < 4; k++) {
                zrA[k] = make_ulonglong2(zacA[2*k], zacA[2*k+1]);
                zrB[k] = make_ulonglong2(zacB[2*k], zacB[2*k+1]);
            }
        }
        __syncthreads();

        // ---- stage Y: y[o][lt*25+w] += sum_v z[lt*25+v][o] * A[s][v][w] ----
        const float* Arow = &s_A[s*(VV*32)];
        #pragma unroll 5
        for (int v = 0; v < VV; v++) {
            float av = Arow[v*32 + lane];   // 0 for lane>=25
            u64 ad = pack2(av, av);
            const ulonglong2* zq = reinterpret_cast<const ulonglong2*>(
                &s_z[(lt*VV + v)*ZST + oby]);
            #pragma unroll
            for (int k = 0; k < 8; k++) {
                ulonglong2 z2 = zq[k];
                fma2(yac[2*k],   z2.x, ad);
                fma2(yac[2*k+1], z2.y, ad);
            }
        }
    }

    // ---- epilogue: y + off + residual, ReLU ----
    if (lane < VV) {
        const int colg = c0 + lt*VV + lane;
        const float* xr = x + (size_t)n*(CC*TD*VV) + colg;
        float* ob = out + (size_t)n*(CC*TD*VV) + colg;
        #pragma unroll
        for (int j = 0; j < 16; j++) {
            int oe = oby + 2*j, oo = oe + 1;
            float2 y2 = unpack2(yac[j]);
            float ve = y2.x + s_off[oe] + xr[(size_t)oe*(TD*VV)];
            float vo = y2.y + s_off[oo] + xr[(size_t)oo*(TD*VV)];
            ob[(size_t)oe*(TD*VV)] = fmaxf(ve, 0.f);
            ob[(size_t)oo*(TD*VV)] = fmaxf(vo, 0.f);
        }
    }
}

// ---------------------------------------------------------------------------
extern "C" void kernel_launch(void* const* d_in, const int* in_sizes, int n_in,
                              void* d_out, int out_size)
{
    const float* x     = (const float*)d_in[0];
    const float* A     = (const float*)d_in[1];
    const float* alpha = (const float*)d_in[2];
    const float* caw   = (const float*)d_in[3];
    const float* cab   = (const float*)d_in[4];
    const float* cbw   = (const float*)d_in[5];
    const float* cbb   = (const float*)d_in[6];
    const float* bag   = (const float*)d_in[7];
    const float* babt  = (const float*)d_in[8];
    const float* bam   = (const float*)d_in[9];
    const float* bav   = (const float*)d_in[10];
    const float* bbg   = (const float*)d_in[11];
    const float* bbbt  = (const float*)d_in[12];
    const float* bbm   = (const float*)d_in[13];
    const float* bbv   = (const float*)d_in[14];
    const float* cdw   = (const float*)d_in[15];
    const float* cdb   = (const float*)d_in[16];
    const float* bng   = (const float*)d_in[17];
    const float* bnb   = (const float*)d_in[18];
    const float* bnm   = (const float*)d_in[19];
    const float* bnv   = (const float*)d_in[20];
    float* out = (float*)d_out;

    const int smemB = (CC*COLS4 + COLS4*ZST + CC*OCn + SS*VV*32 + 64)
                      * sizeof(float);
    cudaFuncSetAttribute(kB, cudaFuncAttributeMaxDynamicSharedMemorySize, smemB);

    kW<<<(SS*OCn*CC + 255)/256, 256>>>(cdw, cdb, bng, bnb, bnm, bnv);
    kConv<<<dim3(NTCB, SS, NN), 256>>>(x, caw, cab, cbw, cbb,
                                       bag, babt, bam, bav,
                                       bbg, bbbt, bbm, bbv);
    kM<<<dim3(NCH, SS, NN), 256>>>();
    kA2<<<(NN*SS*VV*VV + 255)/256, 256>>>(A, alpha);
    kB<<<dim3(NTB4, NN), 256, smemB>>>(x, out);
}